// round 15
// baseline (speedup 1.0000x reference)
#include <cuda_runtime.h>
#include <cstdint>

#define Bq 4
#define Hh 8
#define Nn 1024
#define Dd 64
#define DIMM 512
#define BH (Bq*Hh)
#define QT 8

// scratch (8 MB each)
__device__ float g_Q [BH*Nn*Dd];
__device__ float g_Kt[BH*Dd*Nn];
__device__ float g_V [BH*Nn*Dd];
__device__ float g_O [Bq*Nn*DIMM];

__device__ __forceinline__ uint32_t f2tf(float f) {
    uint32_t u;
    asm("cvt.rna.tf32.f32 %0, %1;" : "=r"(u) : "f"(f));
    return u;
}

__device__ __forceinline__ uint2 tfsplit(float v) {
    uint32_t h = f2tf(v);
    uint2 r;
    r.x = h;
    r.y = f2tf(v - __uint_as_float(h));
    return r;
}

#define MMA_TF32(c, a, b)                                                       \
    asm volatile(                                                               \
        "mma.sync.aligned.m16n8k8.row.col.f32.tf32.tf32.f32 "                   \
        "{%0,%1,%2,%3},{%4,%5,%6,%7},{%8,%9},{%0,%1,%2,%3};"                    \
        : "+f"((c)[0]), "+f"((c)[1]), "+f"((c)[2]), "+f"((c)[3])                \
        : "r"((a)[0]), "r"((a)[1]), "r"((a)[2]), "r"((a)[3]),                   \
          "r"((b)[0]), "r"((b)[1]))

// ---------------------------------------------------------------------------
// 3xTF32 split-precision tensor GEMM. hi/lo tf32 split done ONCE at staging
// (producer side); smem holds uint2{hi,lo} so the consumer mainloop is pure
// LDS.64 + MMA (no ALU cvt in the hot loop).
// Block 128x128xK16, 8 warps (4Mx2N), warp tile 32x64.
// MODE 0: scatter into g_Q / g_Kt / g_V ; MODE 1: out = C + bias
// ---------------------------------------------------------------------------
template<int NCOLS, int MODE>
__global__ __launch_bounds__(256) void mm_3xtf32_kernel(const float* __restrict__ A,
                                                        const float* __restrict__ B,
                                                        const float* __restrict__ bias,
                                                        float* __restrict__ out)
{
    __shared__ uint2 sA[2][2][8][4][32];   // [buf][kt][mt][reg][lane] {hi,lo}
    __shared__ uint2 sB[2][2][16][2][32];  // [buf][kt][nt][reg][lane] {hi,lo}

    const int t    = threadIdx.x;
    const int lane = t & 31, w = t >> 5;
    const int wm = w >> 1, wn = w & 1;        // 4 x 2 warp grid
    const int m0 = blockIdx.y * 128;
    const int n0 = blockIdx.x * 128;

    float acc[2][8][4];
#pragma unroll
    for (int i = 0; i < 2; i++)
#pragma unroll
        for (int j = 0; j < 8; j++)
#pragma unroll
            for (int e = 0; e < 4; e++) acc[i][j][e] = 0.f;

    // ---- loader indexing (fragment placement verified R12/R13) ----
    const int aRow  = t >> 1;
    const int aKt   = t & 1;
    const int amt   = aRow >> 4;
    const int aRegB = (aRow & 15) >> 3;
    const int aLnB  = (aRow & 7) << 2;
    const float* aG = A + (m0 + aRow) * 512 + aKt * 8;

    const int bK    = t >> 5;                 // 0..7
    const int bReg  = bK >> 2;
    const int bKlo  = bK & 3;
    const int bNt   = (t & 31) >> 1;
    const int bLnB  = (t & 1) * 16 + bKlo;
    const float* bG = B + bK * NCOLS + n0 + (t & 31) * 4;

    float4 aV0 = *(const float4*)aG;
    float4 aV1 = *(const float4*)(aG + 4);
    float4 bV0 = *(const float4*)bG;
    float4 bV1 = *(const float4*)(bG + 8 * NCOLS);

    for (int it = 0; it < 32; it++) {
        const int buf = it & 1;
        // stage with tf32 hi/lo split done here (once), packed as uint2
        sA[buf][aKt][amt][aRegB + 0][aLnB + 0] = tfsplit(aV0.x);
        sA[buf][aKt][amt][aRegB + 0][aLnB + 1] = tfsplit(aV0.y);
        sA[buf][aKt][amt][aRegB + 0][aLnB + 2] = tfsplit(aV0.z);
        sA[buf][aKt][amt][aRegB + 0][aLnB + 3] = tfsplit(aV0.w);
        sA[buf][aKt][amt][aRegB + 2][aLnB + 0] = tfsplit(aV1.x);
        sA[buf][aKt][amt][aRegB + 2][aLnB + 1] = tfsplit(aV1.y);
        sA[buf][aKt][amt][aRegB + 2][aLnB + 2] = tfsplit(aV1.z);
        sA[buf][aKt][amt][aRegB + 2][aLnB + 3] = tfsplit(aV1.w);
        sB[buf][0][bNt][bReg][bLnB +  0] = tfsplit(bV0.x);
        sB[buf][0][bNt][bReg][bLnB +  4] = tfsplit(bV0.y);
        sB[buf][0][bNt][bReg][bLnB +  8] = tfsplit(bV0.z);
        sB[buf][0][bNt][bReg][bLnB + 12] = tfsplit(bV0.w);
        sB[buf][1][bNt][bReg][bLnB +  0] = tfsplit(bV1.x);
        sB[buf][1][bNt][bReg][bLnB +  4] = tfsplit(bV1.y);
        sB[buf][1][bNt][bReg][bLnB +  8] = tfsplit(bV1.z);
        sB[buf][1][bNt][bReg][bLnB + 12] = tfsplit(bV1.w);
        __syncthreads();

        if (it + 1 < 32) {
            aG += 16; bG += 16 * NCOLS;
            aV0 = *(const float4*)aG;
            aV1 = *(const float4*)(aG + 4);
            bV0 = *(const float4*)bG;
            bV1 = *(const float4*)(bG + 8 * NCOLS);
        }

#pragma unroll
        for (int kt = 0; kt < 2; kt++) {
            uint32_t ah[2][4], al[2][4], bh[8][2], bl[8][2];
#pragma unroll
            for (int mt = 0; mt < 2; mt++)
#pragma unroll
                for (int r = 0; r < 4; r++) {
                    uint2 v = sA[buf][kt][wm * 2 + mt][r][lane];
                    ah[mt][r] = v.x; al[mt][r] = v.y;
                }
#pragma unroll
            for (int nt = 0; nt < 8; nt++)
#pragma unroll
                for (int r = 0; r < 2; r++) {
                    uint2 v = sB[buf][kt][wn * 8 + nt][r][lane];
                    bh[nt][r] = v.x; bl[nt][r] = v.y;
                }
#pragma unroll
            for (int mt = 0; mt < 2; mt++)
#pragma unroll
                for (int nt = 0; nt < 8; nt++) {
                    MMA_TF32(acc[mt][nt], al[mt], bh[nt]);   // small terms first
                    MMA_TF32(acc[mt][nt], ah[mt], bl[nt]);
                    MMA_TF32(acc[mt][nt], ah[mt], bh[nt]);
                }
        }
    }

    // ---- epilogue ----
    const int r0 = lane >> 2;
    const int cc = (lane & 3) * 2;
#pragma unroll
    for (int mt = 0; mt < 2; mt++) {
#pragma unroll
        for (int nt = 0; nt < 8; nt++) {
            int gcol = n0 + wn * 64 + nt * 8 + cc;
#pragma unroll
            for (int half = 0; half < 2; half++) {
                int grow = m0 + wm * 32 + mt * 16 + r0 + half * 8;
                float v0 = acc[mt][nt][half * 2 + 0];
                float v1 = acc[mt][nt][half * 2 + 1];
                if (MODE == 1) {
                    float2 o = make_float2(v0 + bias[gcol], v1 + bias[gcol + 1]);
                    *(float2*)&out[grow * 512 + gcol] = o;
                } else {
                    int b = grow >> 10, n = grow & 1023;
                    int h = (gcol >> 6) & 7, d = gcol & 63;
                    int bh = b * 8 + h;
                    int part = gcol >> 9;
                    if (part == 0) {
                        *(float2*)&g_Q[(bh * 1024 + n) * 64 + d] = make_float2(v0, v1);
                    } else if (part == 1) {
                        g_Kt[(bh * 64 + d) * 1024 + n]     = v0;
                        g_Kt[(bh * 64 + d + 1) * 1024 + n] = v1;
                    } else {
                        *(float2*)&g_V[(bh * 1024 + n) * 64 + d] = make_float2(v0, v1);
                    }
                }
            }
        }
    }
}

// ---------------------------------------------------------------------------
// Fused attention: per block = (b,h, 8-query tile). Identical to R13 pass.
// ---------------------------------------------------------------------------
__global__ __launch_bounds__(256) void attn_kernel(
    const float* __restrict__ prob,
    const float* __restrict__ t1,
    const float* __restrict__ t2,
    const float* __restrict__ sita,
    const float* __restrict__ Wth,
    float* __restrict__ attn0_out)
{
    __shared__ float qs[QT][64];
    __shared__ float wt[64];
    __shared__ float exA[64];
    __shared__ float traw[QT];
    __shared__ float red[3][QT][8];
    __shared__ float fin_m0[QT], fin_is0[QT], fin_mB[QT], fin_isB[QT];
    __shared__ float fin_mn[QT], fin_thr[QT], fin_id[QT], fin_gate[QT];
    __shared__ union UU {
        float prodt[3969];
        float attnp[QT][1024];
    } U;

    const int t    = threadIdx.x;
    const int lane = t & 31, wid = t >> 5;
    const int bh = blockIdx.y;
    const int b  = bh >> 3, h = bh & 7;
    const int i0 = blockIdx.x * QT;
    const float scale = 0.125f;

    {
        float st = sita[h];
        float factor = 1.0f / (2.0f * st * st + 1e-6f);
        if (t < 63) {
            float dd = (float)(t - 31);
            exA[t] = __expf(-factor * dd * dd * (1.0f / 1024.0f));
        }
    }
    for (int e = t; e < 3969; e += 256)
        U.prodt[e] = t1[e * 8 + h] * t2[e * 8 + h];
    for (int e = t; e < QT * 64; e += 256)
        qs[e >> 6][e & 63] = g_Q[((bh * 1024) + i0 + (e >> 6)) * 64 + (e & 63)];
    if (t < 64) wt[t] = Wth[t];
    __syncthreads();

    {
        int q = wid;
        float v = qs[q][lane] * wt[lane] + qs[q][lane + 32] * wt[lane + 32];
#pragma unroll
        for (int o = 16; o; o >>= 1) v += __shfl_xor_sync(0xffffffffu, v, o);
        if (lane == 0) {
            float sg = 1.0f / (1.0f + __expf(-v));
            traw[q] = sg * 0.11920292202211755f;
        }
    }

    float d0[QT][4];
#pragma unroll
    for (int q = 0; q < QT; q++)
#pragma unroll
        for (int r = 0; r < 4; r++) d0[q][r] = 0.f;

    const float* Kp = &g_Kt[(bh * 64) * 1024 + 4 * t];
#pragma unroll 4
    for (int d = 0; d < 64; d++) {
        float4 kv = *(const float4*)&Kp[d * 1024];
#pragma unroll
        for (int q = 0; q < QT; q++) {
            float qv = qs[q][d];
            d0[q][0] += qv * kv.x; d0[q][1] += qv * kv.y;
            d0[q][2] += qv * kv.z; d0[q][3] += qv * kv.w;
        }
    }

    float dB[QT][4];
    const int ri  = i0 >> 5;
    const int ci0 = i0 & 31;
#pragma unroll
    for (int r = 0; r < 4; r++) {
        int j  = 4 * t + r;
        int rj = j >> 5, cj = j & 31;
        int di = ri - rj;
        float eA = exA[di + 31];
        const float* prow = &U.prodt[(di + 31) * 63];
#pragma unroll
        for (int q = 0; q < QT; q++) {
            int dj = ci0 + q - cj;
            float s0 = d0[q][r] * scale;
            d0[q][r] = s0;
            dB[q][r] = s0 + prow[dj + 31] + 0.01f * (eA * exA[dj + 31]);
        }
    }

#pragma unroll
    for (int q = 0; q < QT; q++) {
        float m0 = fmaxf(fmaxf(d0[q][0], d0[q][1]), fmaxf(d0[q][2], d0[q][3]));
        float mB = fmaxf(fmaxf(dB[q][0], dB[q][1]), fmaxf(dB[q][2], dB[q][3]));
        float mn = fminf(fminf(dB[q][0], dB[q][1]), fminf(dB[q][2], dB[q][3]));
#pragma unroll
        for (int o = 16; o; o >>= 1) {
            m0 = fmaxf(m0, __shfl_xor_sync(0xffffffffu, m0, o));
            mB = fmaxf(mB, __shfl_xor_sync(0xffffffffu, mB, o));
            mn = fminf(mn, __shfl_xor_sync(0xffffffffu, mn, o));
        }
        if (lane == 0) { red[0][q][wid] = m0; red[1][q][wid] = mB; red[2][q][wid] = mn; }
    }
    __syncthreads();
    if (t < QT) {
        float m0 = -1e30f, mB = -1e30f, mn = 1e30f;
#pragma unroll
        for (int w = 0; w < 8; w++) {
            m0 = fmaxf(m0, red[0][t][w]);
            mB = fmaxf(mB, red[1][t][w]);
            mn = fminf(mn, red[2][t][w]);
        }
        fin_m0[t] = m0; fin_mB[t] = mB; fin_mn[t] = mn;
    }
    __syncthreads();

#pragma unroll
    for (int q = 0; q < QT; q++) {
        float m0 = fin_m0[q], mB = fin_mB[q];
        float s0 = 0.f, sB = 0.f;
#pragma unroll
        for (int r = 0; r < 4; r++) {
            d0[q][r] = __expf(d0[q][r] - m0); s0 += d0[q][r];
            dB[q][r] = __expf(dB[q][r] - mB); sB += dB[q][r];
        }
#pragma unroll
        for (int o = 16; o; o >>= 1) {
            s0 += __shfl_xor_sync(0xffffffffu, s0, o);
            sB += __shfl_xor_sync(0xffffffffu, sB, o);
        }
        if (lane == 0) { red[0][q][wid] = s0; red[1][q][wid] = sB; }
    }
    __syncthreads();
    if (t < QT) {
        float s0 = 0.f, sB = 0.f;
#pragma unroll
        for (int w = 0; w < 8; w++) { s0 += red[0][t][w]; sB += red[1][t][w]; }
        float is0 = 1.0f / s0;
        float isB = 1.0f / sB;
        fin_is0[t] = is0; fin_isB[t] = isB;
        float amax = isB;
        float amin = __expf(fin_mn[t] - fin_mB[t]) * isB;
        fin_thr[t]  = amin + traw[t] * (amax - amin);
        fin_gate[t] = (prob[b * 1024 + i0 + t] >= 0.9f) ? 0.0f : 1.0f;
    }
    __syncthreads();

#pragma unroll
    for (int q = 0; q < QT; q++) {
        float is0 = fin_is0[q];
        float4 v = make_float4(d0[q][0] * is0, d0[q][1] * is0,
                               d0[q][2] * is0, d0[q][3] * is0);
        *(float4*)&attn0_out[(size_t)(bh * 1024 + i0 + q) * 1024 + 4 * t] = v;
    }

#pragma unroll
    for (int q = 0; q < QT; q++) {
        float isB = fin_isB[q], th = fin_thr[q], gt = fin_gate[q];
        float s = 0.f;
#pragma unroll
        for (int r = 0; r < 4; r++) {
            float a  = dB[q][r] * isB;
            float ar = (a > th) ? a * gt : 0.0f;
            dB[q][r] = ar;
            s += ar;
        }
#pragma unroll
        for (int o = 16; o; o >>= 1) s += __shfl_xor_sync(0xffffffffu, s, o);
        if (lane == 0) red[0][q][wid] = s;
    }
    __syncthreads();
    if (t < QT) {
        float s = 0.f;
#pragma unroll
        for (int w = 0; w < 8; w++) s += red[0][t][w];
        fin_id[t] = 1.0f / (s + 1e-6f);
    }
    __syncthreads();
#pragma unroll
    for (int q = 0; q < QT; q++) {
        float idn = fin_id[q];
        float4 v = make_float4(dB[q][0] * idn, dB[q][1] * idn,
                               dB[q][2] * idn, dB[q][3] * idn);
        *(float4*)&U.attnp[q][4 * t] = v;
    }
    __syncthreads();

    const int d  = t & 63;
    const int js = t >> 6;
    float acc[QT];
#pragma unroll
    for (int q = 0; q < QT; q++) acc[q] = 0.f;
    const float* Vp = &g_V[(size_t)bh * 1024 * 64 + d];
    for (int jj = js * 256; jj < js * 256 + 256; jj += 4) {
        float4 a[QT];
#pragma unroll
        for (int q = 0; q < QT; q++) a[q] = *(const float4*)&U.attnp[q][jj];
#pragma unroll
        for (int r = 0; r < 4; r++) {
            float v = Vp[(jj + r) * 64];
#pragma unroll
            for (int q = 0; q < QT; q++) {
                float aq = (r == 0) ? a[q].x : (r == 1) ? a[q].y : (r == 2) ? a[q].z : a[q].w;
                acc[q] += aq * v;
            }
        }
    }
    __syncthreads();
    float* osum = (float*)&U;
#pragma unroll
    for (int q = 0; q < QT; q++) osum[(js * QT + q) * 64 + d] = acc[q];
    __syncthreads();
    for (int o = t; o < QT * 64; o += 256) {
        int q = o >> 6, dd = o & 63;
        float v = osum[(0 * QT + q) * 64 + dd] + osum[(1 * QT + q) * 64 + dd]
                + osum[(2 * QT + q) * 64 + dd] + osum[(3 * QT + q) * 64 + dd];
        g_O[((size_t)b * 1024 + i0 + q) * 512 + h * 64 + dd] = v;
    }
}

// ---------------------------------------------------------------------------
extern "C" void kernel_launch(void* const* d_in, const int* in_sizes, int n_in,
                              void* d_out, int out_size)
{
    const float* x    = (const float*)d_in[0];
    const float* prob = (const float*)d_in[1];
    const float* Wqkv = (const float*)d_in[2];
    const float* t1   = (const float*)d_in[3];
    const float* t2   = (const float*)d_in[4];
    const float* sita = (const float*)d_in[5];
    const float* Wth  = (const float*)d_in[6];
    const float* Wout = (const float*)d_in[7];
    const float* bout = (const float*)d_in[8];

    float* out   = (float*)d_out;
    float* attn0 = out + (size_t)Bq * Nn * DIMM;

    float* gO;
    cudaGetSymbolAddress((void**)&gO, g_O);

    mm_3xtf32_kernel<1536, 0><<<dim3(12, 32), 256>>>(x, Wqkv, nullptr, nullptr);
    attn_kernel<<<dim3(Nn / QT, BH), 256>>>(prob, t1, t2, sita, Wth, attn0);
    mm_3xtf32_kernel<512, 1><<<dim3(4, 32), 256>>>(gO, Wout, bout, out);
}

// round 16
// speedup vs baseline: 1.2975x; 1.2975x over previous
#include <cuda_runtime.h>
#include <cstdint>

#define Bq 4
#define Hh 8
#define Nn 1024
#define Dd 64
#define DIMM 512
#define BH (Bq*Hh)
#define QT 8

// scratch (8 MB each)
__device__ float g_Q [BH*Nn*Dd];
__device__ float g_Kt[BH*Dd*Nn];
__device__ float g_V [BH*Nn*Dd];
__device__ float g_O [Bq*Nn*DIMM];

__device__ __forceinline__ uint32_t f2tf(float f) {
    uint32_t u;
    asm("cvt.rna.tf32.f32 %0, %1;" : "=r"(u) : "f"(f));
    return u;
}

#define MMA_TF32(c, a, b)                                                       \
    asm volatile(                                                               \
        "mma.sync.aligned.m16n8k8.row.col.f32.tf32.tf32.f32 "                   \
        "{%0,%1,%2,%3},{%4,%5,%6,%7},{%8,%9},{%0,%1,%2,%3};"                    \
        : "+f"((c)[0]), "+f"((c)[1]), "+f"((c)[2]), "+f"((c)[3])                \
        : "r"((a)[0]), "r"((a)[1]), "r"((a)[2]), "r"((a)[3]),                   \
          "r"((b)[0]), "r"((b)[1]))

// ---------------------------------------------------------------------------
// 3xTF32 split-precision tensor GEMM — R13 structure (float smem, consumer-
// side split, proven 145.9us) + __launch_bounds__(256,2) to force <=128 regs
// for 2 CTAs/SM (occupancy 12.5% -> 25%).
// ---------------------------------------------------------------------------
template<int NCOLS, int MODE>
__global__ __launch_bounds__(256, 2) void mm_3xtf32_kernel(const float* __restrict__ A,
                                                           const float* __restrict__ B,
                                                           const float* __restrict__ bias,
                                                           float* __restrict__ out)
{
    __shared__ float sA[2][2][8][4][33];   // [buf][kt][mt][reg][lane pad33]
    __shared__ float sB[2][2][16][2][33];  // [buf][kt][nt][reg][lane pad33]

    const int t    = threadIdx.x;
    const int lane = t & 31, w = t >> 5;
    const int wm = w >> 1, wn = w & 1;        // 4 x 2 warp grid
    const int m0 = blockIdx.y * 128;
    const int n0 = blockIdx.x * 128;

    float acc[2][8][4];
#pragma unroll
    for (int i = 0; i < 2; i++)
#pragma unroll
        for (int j = 0; j < 8; j++)
#pragma unroll
            for (int e = 0; e < 4; e++) acc[i][j][e] = 0.f;

    const int aRow  = t >> 1;
    const int aKt   = t & 1;
    const int amt   = aRow >> 4;
    const int aRegB = (aRow & 15) >> 3;
    const int aLnB  = (aRow & 7) << 2;
    const float* aG = A + (m0 + aRow) * 512 + aKt * 8;

    const int bK    = t >> 5;
    const int bReg  = bK >> 2;
    const int bKlo  = bK & 3;
    const int bNt   = (t & 31) >> 1;
    const int bLnB  = (t & 1) * 16 + bKlo;
    const float* bG = B + bK * NCOLS + n0 + (t & 31) * 4;

    float4 aV0 = *(const float4*)aG;
    float4 aV1 = *(const float4*)(aG + 4);
    float4 bV0 = *(const float4*)bG;
    float4 bV1 = *(const float4*)(bG + 8 * NCOLS);

    for (int it = 0; it < 32; it++) {
        const int buf = it & 1;
        sA[buf][aKt][amt][aRegB + 0][aLnB + 0] = aV0.x;
        sA[buf][aKt][amt][aRegB + 0][aLnB + 1] = aV0.y;
        sA[buf][aKt][amt][aRegB + 0][aLnB + 2] = aV0.z;
        sA[buf][aKt][amt][aRegB + 0][aLnB + 3] = aV0.w;
        sA[buf][aKt][amt][aRegB + 2][aLnB + 0] = aV1.x;
        sA[buf][aKt][amt][aRegB + 2][aLnB + 1] = aV1.y;
        sA[buf][aKt][amt][aRegB + 2][aLnB + 2] = aV1.z;
        sA[buf][aKt][amt][aRegB + 2][aLnB + 3] = aV1.w;
        sB[buf][0][bNt][bReg][bLnB +  0] = bV0.x;
        sB[buf][0][bNt][bReg][bLnB +  4] = bV0.y;
        sB[buf][0][bNt][bReg][bLnB +  8] = bV0.z;
        sB[buf][0][bNt][bReg][bLnB + 12] = bV0.w;
        sB[buf][1][bNt][bReg][bLnB +  0] = bV1.x;
        sB[buf][1][bNt][bReg][bLnB +  4] = bV1.y;
        sB[buf][1][bNt][bReg][bLnB +  8] = bV1.z;
        sB[buf][1][bNt][bReg][bLnB + 12] = bV1.w;
        __syncthreads();

        if (it + 1 < 32) {
            aG += 16; bG += 16 * NCOLS;
            aV0 = *(const float4*)aG;
            aV1 = *(const float4*)(aG + 4);
            bV0 = *(const float4*)bG;
            bV1 = *(const float4*)(bG + 8 * NCOLS);
        }

#pragma unroll
        for (int kt = 0; kt < 2; kt++) {
            uint32_t ah[2][4], al[2][4], bh[8][2], bl[8][2];
#pragma unroll
            for (int mt = 0; mt < 2; mt++)
#pragma unroll
                for (int r = 0; r < 4; r++) {
                    float v = sA[buf][kt][wm * 2 + mt][r][lane];
                    uint32_t hbits = f2tf(v);
                    ah[mt][r] = hbits;
                    al[mt][r] = f2tf(v - __uint_as_float(hbits));
                }
#pragma unroll
            for (int nt = 0; nt < 8; nt++)
#pragma unroll
                for (int r = 0; r < 2; r++) {
                    float v = sB[buf][kt][wn * 8 + nt][r][lane];
                    uint32_t hbits = f2tf(v);
                    bh[nt][r] = hbits;
                    bl[nt][r] = f2tf(v - __uint_as_float(hbits));
                }
#pragma unroll
            for (int mt = 0; mt < 2; mt++)
#pragma unroll
                for (int nt = 0; nt < 8; nt++) {
                    MMA_TF32(acc[mt][nt], al[mt], bh[nt]);
                    MMA_TF32(acc[mt][nt], ah[mt], bl[nt]);
                    MMA_TF32(acc[mt][nt], ah[mt], bh[nt]);
                }
        }
    }

    const int r0 = lane >> 2;
    const int cc = (lane & 3) * 2;
#pragma unroll
    for (int mt = 0; mt < 2; mt++) {
#pragma unroll
        for (int nt = 0; nt < 8; nt++) {
            int gcol = n0 + wn * 64 + nt * 8 + cc;
#pragma unroll
            for (int half = 0; half < 2; half++) {
                int grow = m0 + wm * 32 + mt * 16 + r0 + half * 8;
                float v0 = acc[mt][nt][half * 2 + 0];
                float v1 = acc[mt][nt][half * 2 + 1];
                if (MODE == 1) {
                    float2 o = make_float2(v0 + bias[gcol], v1 + bias[gcol + 1]);
                    *(float2*)&out[grow * 512 + gcol] = o;
                } else {
                    int b = grow >> 10, n = grow & 1023;
                    int h = (gcol >> 6) & 7, d = gcol & 63;
                    int bh = b * 8 + h;
                    int part = gcol >> 9;
                    if (part == 0) {
                        *(float2*)&g_Q[(bh * 1024 + n) * 64 + d] = make_float2(v0, v1);
                    } else if (part == 1) {
                        g_Kt[(bh * 64 + d) * 1024 + n]     = v0;
                        g_Kt[(bh * 64 + d + 1) * 1024 + n] = v1;
                    } else {
                        *(float2*)&g_V[(bh * 1024 + n) * 64 + d] = make_float2(v0, v1);
                    }
                }
            }
        }
    }
}

// ---------------------------------------------------------------------------
// Fused attention: per block = (b,h, 8-query tile). R13 structure; score loop
// now reads q as float4 (fewer issued instructions, same arithmetic order).
// ---------------------------------------------------------------------------
__global__ __launch_bounds__(256) void attn_kernel(
    const float* __restrict__ prob,
    const float* __restrict__ t1,
    const float* __restrict__ t2,
    const float* __restrict__ sita,
    const float* __restrict__ Wth,
    float* __restrict__ attn0_out)
{
    __shared__ float qs[QT][64];
    __shared__ float wt[64];
    __shared__ float exA[64];
    __shared__ float traw[QT];
    __shared__ float red[3][QT][8];
    __shared__ float fin_m0[QT], fin_is0[QT], fin_mB[QT], fin_isB[QT];
    __shared__ float fin_mn[QT], fin_thr[QT], fin_id[QT], fin_gate[QT];
    __shared__ union UU {
        float prodt[3969];
        float attnp[QT][1024];
    } U;

    const int t    = threadIdx.x;
    const int lane = t & 31, wid = t >> 5;
    const int bh = blockIdx.y;
    const int b  = bh >> 3, h = bh & 7;
    const int i0 = blockIdx.x * QT;
    const float scale = 0.125f;

    {
        float st = sita[h];
        float factor = 1.0f / (2.0f * st * st + 1e-6f);
        if (t < 63) {
            float dd = (float)(t - 31);
            exA[t] = __expf(-factor * dd * dd * (1.0f / 1024.0f));
        }
    }
    for (int e = t; e < 3969; e += 256)
        U.prodt[e] = t1[e * 8 + h] * t2[e * 8 + h];
    for (int e = t; e < QT * 64; e += 256)
        qs[e >> 6][e & 63] = g_Q[((bh * 1024) + i0 + (e >> 6)) * 64 + (e & 63)];
    if (t < 64) wt[t] = Wth[t];
    __syncthreads();

    {
        int q = wid;
        float v = qs[q][lane] * wt[lane] + qs[q][lane + 32] * wt[lane + 32];
#pragma unroll
        for (int o = 16; o; o >>= 1) v += __shfl_xor_sync(0xffffffffu, v, o);
        if (lane == 0) {
            float sg = 1.0f / (1.0f + __expf(-v));
            traw[q] = sg * 0.11920292202211755f;
        }
    }

    // ---- scores: thread owns j = 4t..4t+3; 4-d steps with float4 q reads ----
    float d0[QT][4];
#pragma unroll
    for (int q = 0; q < QT; q++)
#pragma unroll
        for (int r = 0; r < 4; r++) d0[q][r] = 0.f;

    const float* Kp = &g_Kt[(bh * 64) * 1024 + 4 * t];
#pragma unroll 4
    for (int d = 0; d < 64; d += 4) {
        float4 kv0 = *(const float4*)&Kp[(d + 0) * 1024];
        float4 kv1 = *(const float4*)&Kp[(d + 1) * 1024];
        float4 kv2 = *(const float4*)&Kp[(d + 2) * 1024];
        float4 kv3 = *(const float4*)&Kp[(d + 3) * 1024];
#pragma unroll
        for (int q = 0; q < QT; q++) {
            float4 qv = *(const float4*)&qs[q][d];
            d0[q][0] += qv.x * kv0.x; d0[q][1] += qv.x * kv0.y;
            d0[q][2] += qv.x * kv0.z; d0[q][3] += qv.x * kv0.w;
            d0[q][0] += qv.y * kv1.x; d0[q][1] += qv.y * kv1.y;
            d0[q][2] += qv.y * kv1.z; d0[q][3] += qv.y * kv1.w;
            d0[q][0] += qv.z * kv2.x; d0[q][1] += qv.z * kv2.y;
            d0[q][2] += qv.z * kv2.z; d0[q][3] += qv.z * kv2.w;
            d0[q][0] += qv.w * kv3.x; d0[q][1] += qv.w * kv3.y;
            d0[q][2] += qv.w * kv3.z; d0[q][3] += qv.w * kv3.w;
        }
    }

    float dB[QT][4];
    const int ri  = i0 >> 5;
    const int ci0 = i0 & 31;
#pragma unroll
    for (int r = 0; r < 4; r++) {
        int j  = 4 * t + r;
        int rj = j >> 5, cj = j & 31;
        int di = ri - rj;
        float eA = exA[di + 31];
        const float* prow = &U.prodt[(di + 31) * 63];
#pragma unroll
        for (int q = 0; q < QT; q++) {
            int dj = ci0 + q - cj;
            float s0 = d0[q][r] * scale;
            d0[q][r] = s0;
            dB[q][r] = s0 + prow[dj + 31] + 0.01f * (eA * exA[dj + 31]);
        }
    }

#pragma unroll
    for (int q = 0; q < QT; q++) {
        float m0 = fmaxf(fmaxf(d0[q][0], d0[q][1]), fmaxf(d0[q][2], d0[q][3]));
        float mB = fmaxf(fmaxf(dB[q][0], dB[q][1]), fmaxf(dB[q][2], dB[q][3]));
        float mn = fminf(fminf(dB[q][0], dB[q][1]), fminf(dB[q][2], dB[q][3]));
#pragma unroll
        for (int o = 16; o; o >>= 1) {
            m0 = fmaxf(m0, __shfl_xor_sync(0xffffffffu, m0, o));
            mB = fmaxf(mB, __shfl_xor_sync(0xffffffffu, mB, o));
            mn = fminf(mn, __shfl_xor_sync(0xffffffffu, mn, o));
        }
        if (lane == 0) { red[0][q][wid] = m0; red[1][q][wid] = mB; red[2][q][wid] = mn; }
    }
    __syncthreads();
    if (t < QT) {
        float m0 = -1e30f, mB = -1e30f, mn = 1e30f;
#pragma unroll
        for (int w = 0; w < 8; w++) {
            m0 = fmaxf(m0, red[0][t][w]);
            mB = fmaxf(mB, red[1][t][w]);
            mn = fminf(mn, red[2][t][w]);
        }
        fin_m0[t] = m0; fin_mB[t] = mB; fin_mn[t] = mn;
    }
    __syncthreads();

#pragma unroll
    for (int q = 0; q < QT; q++) {
        float m0 = fin_m0[q], mB = fin_mB[q];
        float s0 = 0.f, sB = 0.f;
#pragma unroll
        for (int r = 0; r < 4; r++) {
            d0[q][r] = __expf(d0[q][r] - m0); s0 += d0[q][r];
            dB[q][r] = __expf(dB[q][r] - mB); sB += dB[q][r];
        }
#pragma unroll
        for (int o = 16; o; o >>= 1) {
            s0 += __shfl_xor_sync(0xffffffffu, s0, o);
            sB += __shfl_xor_sync(0xffffffffu, sB, o);
        }
        if (lane == 0) { red[0][q][wid] = s0; red[1][q][wid] = sB; }
    }
    __syncthreads();
    if (t < QT) {
        float s0 = 0.f, sB = 0.f;
#pragma unroll
        for (int w = 0; w < 8; w++) { s0 += red[0][t][w]; sB += red[1][t][w]; }
        float is0 = 1.0f / s0;
        float isB = 1.0f / sB;
        fin_is0[t] = is0; fin_isB[t] = isB;
        float amax = isB;
        float amin = __expf(fin_mn[t] - fin_mB[t]) * isB;
        fin_thr[t]  = amin + traw[t] * (amax - amin);
        fin_gate[t] = (prob[b * 1024 + i0 + t] >= 0.9f) ? 0.0f : 1.0f;
    }
    __syncthreads();

#pragma unroll
    for (int q = 0; q < QT; q++) {
        float is0 = fin_is0[q];
        float4 v = make_float4(d0[q][0] * is0, d0[q][1] * is0,
                               d0[q][2] * is0, d0[q][3] * is0);
        *(float4*)&attn0_out[(size_t)(bh * 1024 + i0 + q) * 1024 + 4 * t] = v;
    }

#pragma unroll
    for (int q = 0; q < QT; q++) {
        float isB = fin_isB[q], th = fin_thr[q], gt = fin_gate[q];
        float s = 0.f;
#pragma unroll
        for (int r = 0; r < 4; r++) {
            float a  = dB[q][r] * isB;
            float ar = (a > th) ? a * gt : 0.0f;
            dB[q][r] = ar;
            s += ar;
        }
#pragma unroll
        for (int o = 16; o; o >>= 1) s += __shfl_xor_sync(0xffffffffu, s, o);
        if (lane == 0) red[0][q][wid] = s;
    }
    __syncthreads();
    if (t < QT) {
        float s = 0.f;
#pragma unroll
        for (int w = 0; w < 8; w++) s += red[0][t][w];
        fin_id[t] = 1.0f / (s + 1e-6f);
    }
    __syncthreads();
#pragma unroll
    for (int q = 0; q < QT; q++) {
        float idn = fin_id[q];
        float4 v = make_float4(dB[q][0] * idn, dB[q][1] * idn,
                               dB[q][2] * idn, dB[q][3] * idn);
        *(float4*)&U.attnp[q][4 * t] = v;
    }
    __syncthreads();

    const int d  = t & 63;
    const int js = t >> 6;
    float acc[QT];
#pragma unroll
    for (int q = 0; q < QT; q++) acc[q] = 0.f;
    const float* Vp = &g_V[(size_t)bh * 1024 * 64 + d];
    for (int jj = js * 256; jj < js * 256 + 256; jj += 4) {
        float4 a[QT];
#pragma unroll
        for (int q = 0; q < QT; q++) a[q] = *(const float4*)&U.attnp[q][jj];
#pragma unroll
        for (int r = 0; r < 4; r++) {
            float v = Vp[(jj + r) * 64];
#pragma unroll
            for (int q = 0; q < QT; q++) {
                float aq = (r == 0) ? a[q].x : (r == 1) ? a[q].y : (r == 2) ? a[q].z : a[q].w;
                acc[q] += aq * v;
            }
        }
    }
    __syncthreads();
    float* osum = (float*)&U;
#pragma unroll
    for (int q = 0; q < QT; q++) osum[(js * QT + q) * 64 + d] = acc[q];
    __syncthreads();
    for (int o = t; o < QT * 64; o += 256) {
        int q = o >> 6, dd = o & 63;
        float v = osum[(0 * QT + q) * 64 + dd] + osum[(1 * QT + q) * 64 + dd]
                + osum[(2 * QT + q) * 64 + dd] + osum[(3 * QT + q) * 64 + dd];
        g_O[((size_t)b * 1024 + i0 + q) * 512 + h * 64 + dd] = v;
    }
}

// ---------------------------------------------------------------------------
extern "C" void kernel_launch(void* const* d_in, const int* in_sizes, int n_in,
                              void* d_out, int out_size)
{
    const float* x    = (const float*)d_in[0];
    const float* prob = (const float*)d_in[1];
    const float* Wqkv = (const float*)d_in[2];
    const float* t1   = (const float*)d_in[3];
    const float* t2   = (const float*)d_in[4];
    const float* sita = (const float*)d_in[5];
    const float* Wth  = (const float*)d_in[6];
    const float* Wout = (const float*)d_in[7];
    const float* bout = (const float*)d_in[8];

    float* out   = (float*)d_out;
    float* attn0 = out + (size_t)Bq * Nn * DIMM;

    float* gO;
    cudaGetSymbolAddress((void**)&gO, g_O);

    mm_3xtf32_kernel<1536, 0><<<dim3(12, 32), 256>>>(x, Wqkv, nullptr, nullptr);
    attn_kernel<<<dim3(Nn / QT, BH), 256>>>(prob, t1, t2, sita, Wth, attn0);
    mm_3xtf32_kernel<512, 1><<<dim3(4, 32), 256>>>(gO, Wout, bout, out);
}